// round 11
// baseline (speedup 1.0000x reference)
#include <cuda_runtime.h>

// Problem constants
#define FD      1024          // feature dim
#define NB      128           // batch / steps
#define KD      4096          // 4 * FD (flattened conv reduction dim)
#define NSPLIT  16            // K-splits for the GEMM (R5 optimum)
#define KCHUNK  256           // KD / NSPLIT
#define GEMM_BLOCKS 256       // 16 n-tiles * 16 k-splits
#define ROWS_PER_BLK 32       // output rows per copy block (128 KB contiguous)
#define COPY_BLOCKS (NB * (FD / ROWS_PER_BLK))   // 128 * 32 = 4096
#define CCHUNKS 4             // dest-chunks per comp row (<=32 dests each)
#define COMP_BLOCKS (NB * CCHUNKS)               // 512
#define COMP_BASE   (GEMM_BLOCKS + COPY_BLOCKS)  // comp blocks scheduled LAST
#define TOTAL_BLOCKS (COMP_BASE + COMP_BLOCKS)   // 4864

// Split-K partial sums: [ksplit][s][1024]  (8 MB, fully rewritten each launch)
__device__ float g_part[NSPLIT * NB * FD];
// Cross-block gate state (BSS-zeroed at load; reset at end of every launch so
// graph replays start clean)
__device__ unsigned g_done;    // # GEMM blocks completed
__device__ unsigned g_taken;   // # comp blocks past the gate + done

// ---------------------------------------------------------------------------
// Single fused kernel. GEMM and comp paths are identical to the R9 winner;
// the copy stage is OUTPUT-CENTRIC: each block owns a contiguous 128 KB
// output span and gathers its source rows (all L2-resident), so concurrent
// CTAs write adjacent DRAM regions instead of ~440 scattered streams.
//   blocks [0, 256)        : split-K GEMM partials -> g_part, signal
//   blocks [256, 4352)     : output-centric gather/copy (comp rows skipped)
//   blocks [4352, 4864)    : gate on GEMM, reduce partials + bias, fill comp
// ---------------------------------------------------------------------------
__global__ __launch_bounds__(256) void fused_kernel(
    const float* __restrict__ inp,   // inputs, viewed as (512, 1024)
    const float* __restrict__ mem,   // memory  (1024, 1024)
    const float* __restrict__ wk,    // kernel, viewed as (4096, 1024)
    const float* __restrict__ bias,  // (1024,)
    float* __restrict__ out)         // (128, 1024, 1024)
{
    if (blockIdx.x < GEMM_BLOCKS) {
        // -------- split-K GEMM:  partial[ks] = OLD[:, kchunk] @ Kflat[kchunk, ntile]
        __shared__ float As[16 * 128];   // [k][s]   (transposed A tile)
        __shared__ float Bs[16 * 64];    // [k][n]
        const int nt  = blockIdx.x & 15;        // n-tile (64 cols)
        const int ks  = blockIdx.x >> 4;        // k-split
        const int tid = threadIdx.x;
        const int tx  = tid & 15;               // 16 threads * 4 cols = 64
        const int ty  = tid >> 4;               // 16 threads * 8 rows = 128
        const float* A = mem + 512 * FD;        // OLD (128, 4096), contiguous

        float acc[8][4];
        #pragma unroll
        for (int m = 0; m < 8; ++m)
            #pragma unroll
            for (int n = 0; n < 4; ++n) acc[m][n] = 0.f;

        const int kc0 = ks * KCHUNK;
        for (int kt = 0; kt < 16; ++kt) {
            const int kb = kc0 + kt * 16;
            // load A tile (128 rows x 16 cols) transposed into As[k][s]
            #pragma unroll
            for (int i = 0; i < 2; ++i) {
                const int f  = tid + i * 256;       // 512 float4 total
                const int s  = f >> 2;
                const int c4 = (f & 3) * 4;
                const float4 v = *reinterpret_cast<const float4*>(A + (size_t)s * KD + kb + c4);
                As[(c4 + 0) * 128 + s] = v.x;
                As[(c4 + 1) * 128 + s] = v.y;
                As[(c4 + 2) * 128 + s] = v.z;
                As[(c4 + 3) * 128 + s] = v.w;
            }
            // load B tile (16 rows x 64 cols)
            {
                const int kk = tid >> 4;
                const int c4 = (tid & 15) * 4;
                *reinterpret_cast<float4*>(&Bs[kk * 64 + c4]) =
                    *reinterpret_cast<const float4*>(wk + (size_t)(kb + kk) * FD + nt * 64 + c4);
            }
            __syncthreads();
            #pragma unroll
            for (int k = 0; k < 16; ++k) {
                const float4 a0 = *reinterpret_cast<const float4*>(&As[k * 128 + ty * 8]);
                const float4 a1 = *reinterpret_cast<const float4*>(&As[k * 128 + ty * 8 + 4]);
                const float4 bv = *reinterpret_cast<const float4*>(&Bs[k * 64 + tx * 4]);
                const float am[8] = {a0.x, a0.y, a0.z, a0.w, a1.x, a1.y, a1.z, a1.w};
                #pragma unroll
                for (int m = 0; m < 8; ++m) {
                    acc[m][0] += am[m] * bv.x;
                    acc[m][1] += am[m] * bv.y;
                    acc[m][2] += am[m] * bv.z;
                    acc[m][3] += am[m] * bv.w;
                }
            }
            __syncthreads();
        }
        #pragma unroll
        for (int m = 0; m < 8; ++m) {
            const float4 r = make_float4(acc[m][0], acc[m][1], acc[m][2], acc[m][3]);
            *reinterpret_cast<float4*>(
                &g_part[(size_t)(ks * NB + ty * 8 + m) * FD + nt * 64 + tx * 4]) = r;
        }
        // signal completion: cta-scope sync chains into tid0's gpu-scope release
        __syncthreads();
        if (threadIdx.x == 0) {
            __threadfence();
            atomicAdd(&g_done, 1u);
        }
    } else if (blockIdx.x < COMP_BASE) {
        // -------- output-centric copy: block owns rows [i0, i0+32) of sample b.
        // Row -> source map (derived from the scan algebra):
        //   i <= 510-b           : mem[i + b + 1]        (conv shift)
        //   511-b <= i <= 511    : comp row (SKIP — comp blocks fill these)
        //   512 <= i <= 1019-4b  : mem[i + 4b + 4]       (short shift)
        //   i >= 1020-4b         : inp[i - 1020 + 4b]    (new inputs)
        const int id = blockIdx.x - GEMM_BLOCKS;
        const int b  = id >> 5;                 // sample 0..127
        const int g  = id & 31;                 // row group 0..31
        const int i0 = g * ROWS_PER_BLK;
        const int t  = threadIdx.x;             // one float4 per thread

        float* dst = out + ((size_t)b * FD + i0) * FD + t * 4;
        #pragma unroll 8
        for (int r = 0; r < ROWS_PER_BLK; ++r) {
            const int i = i0 + r;
            const float* src;
            bool skip = false;
            if (i <= 510 - b) {
                src = mem + (size_t)(i + b + 1) * FD;
            } else if (i <= 511) {
                skip = true;
                src = mem;                       // dummy, not loaded
            } else if (i <= 1019 - 4 * b) {
                src = mem + (size_t)(i + 4 * b + 4) * FD;
            } else {
                src = inp + (size_t)(i - 1020 + 4 * b) * FD;
            }
            if (!skip) {
                const float4 v = __ldg(reinterpret_cast<const float4*>(src + t * 4));
                *reinterpret_cast<float4*>(dst) = v;
            }
            dst += FD;
        }
    } else {
        // -------- comp rows: gate on GEMM, reduce 16 partials + bias, scatter.
        // comp row j goes to out[b][511+j-b] for b in [j, 127]; with d = b-j the
        // dest row is simply 511-d.
        const int id    = blockIdx.x - COMP_BASE;
        const int j     = id >> 2;       // comp row 0..127
        const int chunk = id & 3;        // 4 chunks of <=32 destinations
        const int t     = threadIdx.x;

        // Gate: wait until all 256 GEMM blocks have published g_part.
        // These blocks are scheduled many waves after the GEMM finishes, so in
        // practice the spin count is zero.
        if (threadIdx.x == 0) {
            while (atomicAdd(&g_done, 0u) < (unsigned)GEMM_BLOCKS) __nanosleep(64);
            __threadfence();   // acquire: order g_part reads after the flag
        }
        __syncthreads();

        const int n  = NB - j;           // number of destinations for row j
        const int lo = chunk * 32;
        if (lo < n) {
            const int hi = (n < lo + 32) ? n : (lo + 32);
            float4 s = *reinterpret_cast<const float4*>(bias + t * 4);
            #pragma unroll
            for (int p = 0; p < NSPLIT; ++p) {
                const float4 v = *reinterpret_cast<const float4*>(
                    &g_part[(size_t)(p * NB + j) * FD + t * 4]);
                s.x += v.x; s.y += v.y; s.z += v.z; s.w += v.w;
            }
            for (int d = lo; d < hi; ++d) {
                const int b   = j + d;
                const int row = 511 - d;
                *reinterpret_cast<float4*>(out + ((size_t)b * FD + row) * FD + t * 4) = s;
            }
        }

        // Reset gate state for the next graph replay: the LAST comp block to
        // finish (all 512 have passed the gate by construction of g_taken)
        // zeroes both counters.
        __syncthreads();
        if (threadIdx.x == 0) {
            const unsigned tk = atomicAdd(&g_taken, 1u);
            if (tk == (unsigned)(COMP_BLOCKS - 1)) {
                g_done  = 0u;
                g_taken = 0u;
                __threadfence();
            }
        }
    }
}

extern "C" void kernel_launch(void* const* d_in, const int* in_sizes, int n_in,
                              void* d_out, int out_size)
{
    const float* inp  = (const float*)d_in[0];   // (128,4,1024) = (512,1024) flat
    const float* mem  = (const float*)d_in[1];   // (1024,1024)
    const float* wk   = (const float*)d_in[2];   // (4,1024,1024) = (4096,1024) flat
    const float* bias = (const float*)d_in[3];   // (1024,)
    float* out = (float*)d_out;                  // (128,1024,1024)

    fused_kernel<<<TOTAL_BLOCKS, 256>>>(inp, mem, wk, bias, out);
}

// round 12
// speedup vs baseline: 1.1895x; 1.1895x over previous
#include <cuda_runtime.h>

// Problem constants
#define FD      1024          // feature dim
#define NB      128           // batch / steps
#define KD      4096          // 4 * FD (flattened conv reduction dim)
#define NSPLIT  16            // K-splits for the GEMM (R5 optimum)
#define KCHUNK  256           // KD / NSPLIT
#define GEMM_BLOCKS 256       // 16 n-tiles * 16 k-splits
#define NSRC    1535          // 511 conv + 512 short + 512 input source rows
#define CHUNKS  2             // dest-chunks per scatter source row (<=64 dests)
#define CCHUNKS 4             // dest-chunks per comp row (<=32 dests each)
#define SCAT_BLOCKS (NSRC * CHUNKS)              // 3070
#define COMP_BLOCKS (NB * CCHUNKS)               // 512
#define COMP_BASE   (GEMM_BLOCKS + SCAT_BLOCKS)  // comp blocks scheduled LAST
#define TOTAL_BLOCKS (COMP_BASE + COMP_BLOCKS)   // 3838

// Split-K partial sums: [ksplit][s][1024]  (8 MB, fully rewritten each launch)
__device__ float g_part[NSPLIT * NB * FD];
// Cross-block gate state (BSS-zeroed at load; reset at end of every launch so
// graph replays start clean)
__device__ unsigned g_done;    // # GEMM blocks completed
__device__ unsigned g_taken;   // # comp blocks past the gate + done

// ---------------------------------------------------------------------------
// Single fused kernel — R9/R10 winner with one change: 64 destinations per
// scatter block (CHUNKS 4 -> 2), halving redundant source reads through L2
// (the proven limiter direction) and halving block front-stall episodes.
//   blocks [0, 256)             : split-K GEMM partials  -> g_part, signal
//   blocks [256, 256+3070)      : source-centric scatter of all copy rows
//   blocks [3326, 3838)         : gate on GEMM, reduce partials + bias,
//                                 scatter comp rows
// ---------------------------------------------------------------------------
__global__ __launch_bounds__(256) void fused_kernel(
    const float* __restrict__ inp,   // inputs, viewed as (512, 1024)
    const float* __restrict__ mem,   // memory  (1024, 1024)
    const float* __restrict__ wk,    // kernel, viewed as (4096, 1024)
    const float* __restrict__ bias,  // (1024,)
    float* __restrict__ out)         // (128, 1024, 1024)
{
    if (blockIdx.x < GEMM_BLOCKS) {
        // -------- split-K GEMM:  partial[ks] = OLD[:, kchunk] @ Kflat[kchunk, ntile]
        __shared__ float As[16 * 128];   // [k][s]   (transposed A tile)
        __shared__ float Bs[16 * 64];    // [k][n]
        const int nt  = blockIdx.x & 15;        // n-tile (64 cols)
        const int ks  = blockIdx.x >> 4;        // k-split
        const int tid = threadIdx.x;
        const int tx  = tid & 15;               // 16 threads * 4 cols = 64
        const int ty  = tid >> 4;               // 16 threads * 8 rows = 128
        const float* A = mem + 512 * FD;        // OLD (128, 4096), contiguous

        float acc[8][4];
        #pragma unroll
        for (int m = 0; m < 8; ++m)
            #pragma unroll
            for (int n = 0; n < 4; ++n) acc[m][n] = 0.f;

        const int kc0 = ks * KCHUNK;
        for (int kt = 0; kt < 16; ++kt) {
            const int kb = kc0 + kt * 16;
            // load A tile (128 rows x 16 cols) transposed into As[k][s]
            #pragma unroll
            for (int i = 0; i < 2; ++i) {
                const int f  = tid + i * 256;       // 512 float4 total
                const int s  = f >> 2;
                const int c4 = (f & 3) * 4;
                const float4 v = *reinterpret_cast<const float4*>(A + (size_t)s * KD + kb + c4);
                As[(c4 + 0) * 128 + s] = v.x;
                As[(c4 + 1) * 128 + s] = v.y;
                As[(c4 + 2) * 128 + s] = v.z;
                As[(c4 + 3) * 128 + s] = v.w;
            }
            // load B tile (16 rows x 64 cols)
            {
                const int kk = tid >> 4;
                const int c4 = (tid & 15) * 4;
                *reinterpret_cast<float4*>(&Bs[kk * 64 + c4]) =
                    *reinterpret_cast<const float4*>(wk + (size_t)(kb + kk) * FD + nt * 64 + c4);
            }
            __syncthreads();
            #pragma unroll
            for (int k = 0; k < 16; ++k) {
                const float4 a0 = *reinterpret_cast<const float4*>(&As[k * 128 + ty * 8]);
                const float4 a1 = *reinterpret_cast<const float4*>(&As[k * 128 + ty * 8 + 4]);
                const float4 bv = *reinterpret_cast<const float4*>(&Bs[k * 64 + tx * 4]);
                const float am[8] = {a0.x, a0.y, a0.z, a0.w, a1.x, a1.y, a1.z, a1.w};
                #pragma unroll
                for (int m = 0; m < 8; ++m) {
                    acc[m][0] += am[m] * bv.x;
                    acc[m][1] += am[m] * bv.y;
                    acc[m][2] += am[m] * bv.z;
                    acc[m][3] += am[m] * bv.w;
                }
            }
            __syncthreads();
        }
        #pragma unroll
        for (int m = 0; m < 8; ++m) {
            const float4 r = make_float4(acc[m][0], acc[m][1], acc[m][2], acc[m][3]);
            *reinterpret_cast<float4*>(
                &g_part[(size_t)(ks * NB + ty * 8 + m) * FD + nt * 64 + tx * 4]) = r;
        }
        // signal completion: cta-scope sync chains into tid0's gpu-scope release
        __syncthreads();
        if (threadIdx.x == 0) {
            __threadfence();
            atomicAdd(&g_done, 1u);
        }
    } else if (blockIdx.x < COMP_BASE) {
        // -------- source-centric scatter of all non-comp output rows
        const int id    = blockIdx.x - GEMM_BLOCKS;
        const int sid   = id >> 1;       // source row id
        const int chunk = id & 1;        // which group of <=64 destinations
        const int t     = threadIdx.x;   // one float4 per thread (256 * 4 = 1024)

        const float* src;
        int nb, rbase, rstep;
        if (sid < 511) {
            // conv-memory row c = sid+1 -> out[b][c-1-b] for b in [0, min(c-1,127)]
            const int c = sid + 1;
            nb    = (c < 128) ? c : 128;
            rbase = c - 1;
            rstep = -1;
            src   = mem + (size_t)c * FD;
        } else if (sid < 1023) {
            // short-memory row h -> out[b][508+h-4b] for b in [0, h/4-1]
            const int h = sid - 511;
            nb    = h >> 2;
            rbase = 508 + h;
            rstep = -4;
            src   = mem + (size_t)(512 + h) * FD;
        } else {
            // input flat row x -> out[b][1020+x-4b] for b in [x/4, 127]
            const int x = sid - 1023;
            const int b0 = x >> 2;
            nb    = 128 - b0;
            rbase = 1020 + x;   // row = rbase + rstep*b
            rstep = -4;
            src   = inp + (size_t)x * FD;
        }
        const int bfirst = (sid >= 1023) ? ((sid - 1023) >> 2) : 0;
        const int lo = chunk * 64;
        if (lo >= nb) return;
        const int hi = (nb < lo + 64) ? nb : (lo + 64);

        const float4 v = *reinterpret_cast<const float4*>(src + t * 4);
        for (int d = lo; d < hi; ++d) {
            const int b   = bfirst + d;
            const int row = rbase + rstep * b;
            *reinterpret_cast<float4*>(out + ((size_t)b * FD + row) * FD + t * 4) = v;
        }
    } else {
        // -------- comp rows: gate on GEMM, reduce 16 partials + bias, scatter.
        // comp row j goes to out[b][511+j-b] for b in [j, 127]; with d = b-j the
        // dest row is simply 511-d.
        const int id    = blockIdx.x - COMP_BASE;
        const int j     = id >> 2;       // comp row 0..127
        const int chunk = id & 3;        // 4 chunks of <=32 destinations
        const int t     = threadIdx.x;

        // Gate: wait until all 256 GEMM blocks have published g_part.
        // These blocks are scheduled many waves after the GEMM finishes, so in
        // practice the spin count is zero.
        if (threadIdx.x == 0) {
            while (atomicAdd(&g_done, 0u) < (unsigned)GEMM_BLOCKS) __nanosleep(64);
            __threadfence();   // acquire: order g_part reads after the flag
        }
        __syncthreads();

        const int n  = NB - j;           // number of destinations for row j
        const int lo = chunk * 32;
        if (lo < n) {
            const int hi = (n < lo + 32) ? n : (lo + 32);
            float4 s = *reinterpret_cast<const float4*>(bias + t * 4);
            #pragma unroll
            for (int p = 0; p < NSPLIT; ++p) {
                const float4 v = *reinterpret_cast<const float4*>(
                    &g_part[(size_t)(p * NB + j) * FD + t * 4]);
                s.x += v.x; s.y += v.y; s.z += v.z; s.w += v.w;
            }
            for (int d = lo; d < hi; ++d) {
                const int b   = j + d;
                const int row = 511 - d;
                *reinterpret_cast<float4*>(out + ((size_t)b * FD + row) * FD + t * 4) = s;
            }
        }

        // Reset gate state for the next graph replay: the LAST comp block to
        // finish (all 512 have passed the gate by construction of g_taken)
        // zeroes both counters.
        __syncthreads();
        if (threadIdx.x == 0) {
            const unsigned tk = atomicAdd(&g_taken, 1u);
            if (tk == (unsigned)(COMP_BLOCKS - 1)) {
                g_done  = 0u;
                g_taken = 0u;
                __threadfence();
            }
        }
    }
}

extern "C" void kernel_launch(void* const* d_in, const int* in_sizes, int n_in,
                              void* d_out, int out_size)
{
    const float* inp  = (const float*)d_in[0];   // (128,4,1024) = (512,1024) flat
    const float* mem  = (const float*)d_in[1];   // (1024,1024)
    const float* wk   = (const float*)d_in[2];   // (4,1024,1024) = (4096,1024) flat
    const float* bias = (const float*)d_in[3];   // (1024,)
    float* out = (float*)d_out;                  // (128,1024,1024)

    fused_kernel<<<TOTAL_BLOCKS, 256>>>(inp, mem, wk, bias, out);
}

// round 13
// speedup vs baseline: 1.2414x; 1.0436x over previous
#include <cuda_runtime.h>

// Problem constants
#define FD      1024          // feature dim
#define NB      128           // batch / steps
#define KD      4096          // 4 * FD (flattened conv reduction dim)
#define NSPLIT  16            // K-splits for the GEMM (R5 optimum)
#define KCHUNK  256           // KD / NSPLIT
#define GEMM_BLOCKS 256       // 16 n-tiles * 16 k-splits
#define NSRC    1535          // 511 conv + 512 short + 512 input source rows
#define CHUNKS  4             // chunks per scatter source row (strided dests)
#define CCHUNKS 4             // chunks per comp row (strided dests)
#define SCAT_BLOCKS (NSRC * CHUNKS)              // 6140
#define COMP_BLOCKS (NB * CCHUNKS)               // 512
#define COMP_BASE   (GEMM_BLOCKS + SCAT_BLOCKS)  // comp blocks scheduled LAST
#define TOTAL_BLOCKS (COMP_BASE + COMP_BLOCKS)   // 6908

// Split-K partial sums: [ksplit][s][1024]  (8 MB, fully rewritten each launch)
__device__ float g_part[NSPLIT * NB * FD];
// Cross-block gate state (BSS-zeroed at load; reset at end of every launch so
// graph replays start clean)
__device__ unsigned g_done;    // # GEMM blocks completed
__device__ unsigned g_taken;   // # comp blocks past the gate + done

// ---------------------------------------------------------------------------
// Single fused kernel — R10 champion configuration with STRIDED chunking:
// chunk q of a source row handles destinations d = q, q+4, q+8, ... so all
// four chunks carry equal work (blocked chunking left ~25% of blocks empty
// or partial, wasting wave slots and raggedizing the final wave).
//   blocks [0, 256)             : split-K GEMM partials  -> g_part, signal
//   blocks [256, 256+6140)      : source-centric scatter of all copy rows
//   blocks [6396, 6908)         : gate on GEMM, reduce partials + bias,
//                                 scatter comp rows
// ---------------------------------------------------------------------------
__global__ __launch_bounds__(256) void fused_kernel(
    const float* __restrict__ inp,   // inputs, viewed as (512, 1024)
    const float* __restrict__ mem,   // memory  (1024, 1024)
    const float* __restrict__ wk,    // kernel, viewed as (4096, 1024)
    const float* __restrict__ bias,  // (1024,)
    float* __restrict__ out)         // (128, 1024, 1024)
{
    if (blockIdx.x < GEMM_BLOCKS) {
        // -------- split-K GEMM:  partial[ks] = OLD[:, kchunk] @ Kflat[kchunk, ntile]
        __shared__ float As[16 * 128];   // [k][s]   (transposed A tile)
        __shared__ float Bs[16 * 64];    // [k][n]
        const int nt  = blockIdx.x & 15;        // n-tile (64 cols)
        const int ks  = blockIdx.x >> 4;        // k-split
        const int tid = threadIdx.x;
        const int tx  = tid & 15;               // 16 threads * 4 cols = 64
        const int ty  = tid >> 4;               // 16 threads * 8 rows = 128
        const float* A = mem + 512 * FD;        // OLD (128, 4096), contiguous

        float acc[8][4];
        #pragma unroll
        for (int m = 0; m < 8; ++m)
            #pragma unroll
            for (int n = 0; n < 4; ++n) acc[m][n] = 0.f;

        const int kc0 = ks * KCHUNK;
        for (int kt = 0; kt < 16; ++kt) {
            const int kb = kc0 + kt * 16;
            // load A tile (128 rows x 16 cols) transposed into As[k][s]
            #pragma unroll
            for (int i = 0; i < 2; ++i) {
                const int f  = tid + i * 256;       // 512 float4 total
                const int s  = f >> 2;
                const int c4 = (f & 3) * 4;
                const float4 v = *reinterpret_cast<const float4*>(A + (size_t)s * KD + kb + c4);
                As[(c4 + 0) * 128 + s] = v.x;
                As[(c4 + 1) * 128 + s] = v.y;
                As[(c4 + 2) * 128 + s] = v.z;
                As[(c4 + 3) * 128 + s] = v.w;
            }
            // load B tile (16 rows x 64 cols)
            {
                const int kk = tid >> 4;
                const int c4 = (tid & 15) * 4;
                *reinterpret_cast<float4*>(&Bs[kk * 64 + c4]) =
                    *reinterpret_cast<const float4*>(wk + (size_t)(kb + kk) * FD + nt * 64 + c4);
            }
            __syncthreads();
            #pragma unroll
            for (int k = 0; k < 16; ++k) {
                const float4 a0 = *reinterpret_cast<const float4*>(&As[k * 128 + ty * 8]);
                const float4 a1 = *reinterpret_cast<const float4*>(&As[k * 128 + ty * 8 + 4]);
                const float4 bv = *reinterpret_cast<const float4*>(&Bs[k * 64 + tx * 4]);
                const float am[8] = {a0.x, a0.y, a0.z, a0.w, a1.x, a1.y, a1.z, a1.w};
                #pragma unroll
                for (int m = 0; m < 8; ++m) {
                    acc[m][0] += am[m] * bv.x;
                    acc[m][1] += am[m] * bv.y;
                    acc[m][2] += am[m] * bv.z;
                    acc[m][3] += am[m] * bv.w;
                }
            }
            __syncthreads();
        }
        #pragma unroll
        for (int m = 0; m < 8; ++m) {
            const float4 r = make_float4(acc[m][0], acc[m][1], acc[m][2], acc[m][3]);
            *reinterpret_cast<float4*>(
                &g_part[(size_t)(ks * NB + ty * 8 + m) * FD + nt * 64 + tx * 4]) = r;
        }
        // signal completion: cta-scope sync chains into tid0's gpu-scope release
        __syncthreads();
        if (threadIdx.x == 0) {
            __threadfence();
            atomicAdd(&g_done, 1u);
        }
    } else if (blockIdx.x < COMP_BASE) {
        // -------- source-centric scatter of all non-comp output rows
        const int id    = blockIdx.x - GEMM_BLOCKS;
        const int sid   = id >> 2;       // source row id
        const int chunk = id & 3;        // strided dest class: d = chunk + 4k
        const int t     = threadIdx.x;   // one float4 per thread (256 * 4 = 1024)

        const float* src;
        int nb, rbase, rstep;
        if (sid < 511) {
            // conv-memory row c = sid+1 -> out[b][c-1-b] for b in [0, min(c-1,127)]
            const int c = sid + 1;
            nb    = (c < 128) ? c : 128;
            rbase = c - 1;
            rstep = -1;
            src   = mem + (size_t)c * FD;
        } else if (sid < 1023) {
            // short-memory row h -> out[b][508+h-4b] for b in [0, h/4-1]
            const int h = sid - 511;
            nb    = h >> 2;
            rbase = 508 + h;
            rstep = -4;
            src   = mem + (size_t)(512 + h) * FD;
        } else {
            // input flat row x -> out[b][1020+x-4b] for b in [x/4, 127]
            const int x = sid - 1023;
            const int b0 = x >> 2;
            nb    = 128 - b0;
            rbase = 1020 + x;   // row = rbase + rstep*b
            rstep = -4;
            src   = inp + (size_t)x * FD;
        }
        const int bfirst = (sid >= 1023) ? ((sid - 1023) >> 2) : 0;
        if (chunk >= nb) return;

        const float4 v = *reinterpret_cast<const float4*>(src + t * 4);
        for (int d = chunk; d < nb; d += CHUNKS) {
            const int b   = bfirst + d;
            const int row = rbase + rstep * b;
            *reinterpret_cast<float4*>(out + ((size_t)b * FD + row) * FD + t * 4) = v;
        }
    } else {
        // -------- comp rows: gate on GEMM, reduce 16 partials + bias, scatter.
        // comp row j goes to out[b][511+j-b] for b in [j, 127]; with d = b-j the
        // dest row is simply 511-d.
        const int id    = blockIdx.x - COMP_BASE;
        const int j     = id >> 2;       // comp row 0..127
        const int chunk = id & 3;        // strided dest class: d = chunk + 4k
        const int t     = threadIdx.x;

        // Gate: wait until all 256 GEMM blocks have published g_part.
        // These blocks are scheduled many waves after the GEMM finishes, so in
        // practice the spin count is zero.
        if (threadIdx.x == 0) {
            while (atomicAdd(&g_done, 0u) < (unsigned)GEMM_BLOCKS) __nanosleep(64);
            __threadfence();   // acquire: order g_part reads after the flag
        }
        __syncthreads();

        const int n = NB - j;            // number of destinations for row j
        if (chunk < n) {
            float4 s = *reinterpret_cast<const float4*>(bias + t * 4);
            #pragma unroll
            for (int p = 0; p < NSPLIT; ++p) {
                const float4 v = *reinterpret_cast<const float4*>(
                    &g_part[(size_t)(p * NB + j) * FD + t * 4]);
                s.x += v.x; s.y += v.y; s.z += v.z; s.w += v.w;
            }
            for (int d = chunk; d < n; d += CCHUNKS) {
                const int b   = j + d;
                const int row = 511 - d;
                *reinterpret_cast<float4*>(out + ((size_t)b * FD + row) * FD + t * 4) = s;
            }
        }

        // Reset gate state for the next graph replay: the LAST comp block to
        // finish (all 512 have passed the gate by construction of g_taken)
        // zeroes both counters.
        __syncthreads();
        if (threadIdx.x == 0) {
            const unsigned tk = atomicAdd(&g_taken, 1u);
            if (tk == (unsigned)(COMP_BLOCKS - 1)) {
                g_done  = 0u;
                g_taken = 0u;
                __threadfence();
            }
        }
    }
}

extern "C" void kernel_launch(void* const* d_in, const int* in_sizes, int n_in,
                              void* d_out, int out_size)
{
    const float* inp  = (const float*)d_in[0];   // (128,4,1024) = (512,1024) flat
    const float* mem  = (const float*)d_in[1];   // (1024,1024)
    const float* wk   = (const float*)d_in[2];   // (4,1024,1024) = (4096,1024) flat
    const float* bias = (const float*)d_in[3];   // (1024,)
    float* out = (float*)d_out;                  // (128,1024,1024)

    fused_kernel<<<TOTAL_BLOCKS, 256>>>(inp, mem, wk, bias, out);
}